// round 13
// baseline (speedup 1.0000x reference)
#include <cuda_runtime.h>
#include <cuda_fp16.h>
#include <math.h>
#include <stdint.h>

#define NN 20000
#define EE 320000
#define DIN 128
#define DHID 128
#define DOUT 64
#define HEADS 8
#define GG 64

// ---------------- scratch ----------------
__device__ int    g_deg[NN];
__device__ int    g_rowstart[NN + 1];
__device__ int    g_cursor[NN];
__device__ int    g_csr_src[EE];
__device__ float  g_dinv[NN];
__device__ float  g_sinv[NN];
__device__ __half g_tmp[NN * DHID];            // fp16 GCN pre-agg table (gathered)
__device__ float  g_h0[NN * DHID];
__device__ float  g_h1[NN * DHID];
__device__ __half g_gath[NN * HEADS * DOUT];   // fp16 GAT features (gathered)
__device__ float  g_als[NN * HEADS];
__device__ float  g_ald[NN * HEADS];
__device__ __half g_ev[EE * HEADS];            // fp16 exp(logit) per edge
__device__ float  g_gatout[NN * DOUT];
__device__ float  g_agg[NN * DHID];
__device__ float  g_s1[NN * DOUT];
__device__ float  g_agg2[NN * DOUT];
__device__ float  g_s2[NN * DOUT];
__device__ float  g_pooled[GG * 128];
__device__ float  g_cnt[GG];

// ---------------- helpers ----------------
__device__ __forceinline__ float4 f4mul(float4 a, float s) {
    return make_float4(a.x * s, a.y * s, a.z * s, a.w * s);
}
__device__ __forceinline__ void f4fma(float4& acc, float4 a, float s) {
    acc.x += a.x * s; acc.y += a.y * s; acc.z += a.z * s; acc.w += a.w * s;
}
__device__ __forceinline__ void f4add(float4& acc, float4 a) {
    acc.x += a.x; acc.y += a.y; acc.z += a.z; acc.w += a.w;
}
struct F8 { float v[8]; };
__device__ __forceinline__ F8 ld8(const float* p) {
    F8 r;
    float4 a = *(const float4*)p;
    float4 b = *(const float4*)(p + 4);
    r.v[0]=a.x; r.v[1]=a.y; r.v[2]=a.z; r.v[3]=a.w;
    r.v[4]=b.x; r.v[5]=b.y; r.v[6]=b.z; r.v[7]=b.w;
    return r;
}
__device__ __forceinline__ F8 ldh8(const __half* p) {
    uint4 u = *(const uint4*)p;
    F8 r;
    float2 f;
    f = __half22float2(*(__half2*)&u.x); r.v[0]=f.x; r.v[1]=f.y;
    f = __half22float2(*(__half2*)&u.y); r.v[2]=f.x; r.v[3]=f.y;
    f = __half22float2(*(__half2*)&u.z); r.v[4]=f.x; r.v[5]=f.y;
    f = __half22float2(*(__half2*)&u.w); r.v[6]=f.x; r.v[7]=f.y;
    return r;
}
__device__ __forceinline__ uint32_t pack_h2(float a, float b) {
    __half2 h = __floats2half2_rn(a, b);
    return *(uint32_t*)&h;
}
__device__ __forceinline__ uint4 cvt8(float4 a, float4 b) {
    return make_uint4(pack_h2(a.x, a.y), pack_h2(a.z, a.w),
                      pack_h2(b.x, b.y), pack_h2(b.z, b.w));
}
__device__ __forceinline__ float4 h4_to_f4(uint2 v) {
    float2 fa = __half22float2(*(__half2*)&v.x);
    float2 fb = __half22float2(*(__half2*)&v.y);
    return make_float4(fa.x, fa.y, fb.x, fb.y);
}

__device__ __forceinline__ void ldm_x4(uint32_t& r0, uint32_t& r1, uint32_t& r2, uint32_t& r3,
                                       uint32_t addr) {
    asm volatile("ldmatrix.sync.aligned.m8n8.x4.shared.b16 {%0,%1,%2,%3}, [%4];\n"
                 : "=r"(r0), "=r"(r1), "=r"(r2), "=r"(r3) : "r"(addr));
}
__device__ __forceinline__ void ldm_x4_t(uint32_t& r0, uint32_t& r1, uint32_t& r2, uint32_t& r3,
                                         uint32_t addr) {
    asm volatile("ldmatrix.sync.aligned.m8n8.x4.trans.shared.b16 {%0,%1,%2,%3}, [%4];\n"
                 : "=r"(r0), "=r"(r1), "=r"(r2), "=r"(r3) : "r"(addr));
}
__device__ __forceinline__ void mma_f16(float* d, uint32_t a0, uint32_t a1, uint32_t a2,
                                        uint32_t a3, uint32_t b0, uint32_t b1) {
    asm volatile(
        "mma.sync.aligned.m16n8k16.row.col.f32.f16.f16.f32 "
        "{%0,%1,%2,%3}, {%4,%5,%6,%7}, {%8,%9}, {%0,%1,%2,%3};\n"
        : "+f"(d[0]), "+f"(d[1]), "+f"(d[2]), "+f"(d[3])
        : "r"(a0), "r"(a1), "r"(a2), "r"(a3), "r"(b0), "r"(b1));
}

// ---------------- fp16 tensor-core GEMM, BM=128 x BN=64, 8 warps (256 thr) ----------------
// C[N,KTOT] = A1@W1 (+A2@W2) (+b) (relu?) (attention logits if ATT; fp16 C if HALFC)
// A staged full-K; B staged in 32-k chunks (smem: As 128x(M+8), Bs 32x72 -> <=40KB).
template<int M, int KTOT, bool DUAL, bool RELU, bool ATT, bool HALFC>
__global__ void __launch_bounds__(256, 4)
gemm_f16(const float* __restrict__ A1, const float* __restrict__ W1,
         const float* __restrict__ A2, const float* __restrict__ W2,
         const float* __restrict__ b, void* __restrict__ Cv, int N,
         const float* __restrict__ asrc, const float* __restrict__ adst,
         float* __restrict__ als, float* __restrict__ ald) {
    constexpr int ASTRH = M + 8;    // fp16 units; row pitch bytes %16==0
    constexpr int BSTRH = 72;
    __shared__ __align__(16) __half As[128 * ASTRH];
    __shared__ __align__(16) __half Bs[32 * BSTRH];
    int tid = threadIdx.x;
    int warp = tid >> 5, lane = tid & 31;
    int grp = lane >> 2, qid = lane & 3;
    int row0 = blockIdx.x * 128;
    int bn0 = blockIdx.y * 64;
    int mrow = warp * 16;

    float acc[8][4];
#pragma unroll
    for (int j = 0; j < 8; j++)
#pragma unroll
        for (int c = 0; c < 4; c++) acc[j][c] = 0.f;

    // ldmatrix lane base addresses
    int lt = lane >> 3, lr = lane & 7;
    uint32_t a_base = (uint32_t)__cvta_generic_to_shared(
        &As[(mrow + ((lt & 1) << 3) + lr) * ASTRH + ((lt >> 1) << 3)]);
    uint32_t b_base = (uint32_t)__cvta_generic_to_shared(
        &Bs[(((lt & 1) << 3) + lr) * BSTRH + ((lt >> 1) << 3)]);

    const float4 z4 = make_float4(0.f, 0.f, 0.f, 0.f);

    auto stage_a = [&](const float* A) {
        // 128 rows x (M/8) 16B segments; 256 threads
#pragma unroll
        for (int i = 0; i < M / 16; i++) {
            int q = tid + i * 256;
            int row = q / (M / 8), seg = q % (M / 8);
            float4 va = z4, vb = z4;
            if (row0 + row < N) {
                const float* src = A + (size_t)(row0 + row) * M + seg * 8;
                va = *(const float4*)src;
                vb = *(const float4*)(src + 4);
            }
            *(uint4*)&As[row * ASTRH + seg * 8] = cvt8(va, vb);
        }
    };
    auto stage_b = [&](const float* W, int kc) {
        // 32 rows x 8 segments = 256 items; one per thread
        int r = tid >> 3, seg = tid & 7;
        const float* src = W + (size_t)(kc + r) * KTOT + bn0 + seg * 8;
        float4 va = *(const float4*)src;
        float4 vb = *(const float4*)(src + 4);
        *(uint4*)&Bs[r * BSTRH + seg * 8] = cvt8(va, vb);
    };
    auto mma_chunk = [&](int kc) {
#pragma unroll
        for (int ks2 = 0; ks2 < 2; ks2++) {
            uint32_t a0, a1, a2, a3;
            ldm_x4(a0, a1, a2, a3, a_base + (uint32_t)(kc + ks2 * 16) * 2);
#pragma unroll
            for (int jp = 0; jp < 4; jp++) {
                uint32_t b0, b1, b2, b3;
                ldm_x4_t(b0, b1, b2, b3,
                         b_base + (uint32_t)(ks2 * 16 * BSTRH + jp * 16) * 2);
                mma_f16(acc[jp * 2],     a0, a1, a2, a3, b0, b1);
                mma_f16(acc[jp * 2 + 1], a0, a1, a2, a3, b2, b3);
            }
        }
    };

    stage_a(A1);
#pragma unroll
    for (int kc = 0; kc < M; kc += 32) {
        __syncthreads();
        stage_b(W1, kc);
        __syncthreads();
        mma_chunk(kc);
    }
    if (DUAL) {
        __syncthreads();
        stage_a(A2);
#pragma unroll
        for (int kc = 0; kc < M; kc += 32) {
            __syncthreads();
            stage_b(W2, kc);
            __syncthreads();
            mma_chunk(kc);
        }
    }

    // ---- epilogue (attention vectors loaded inline to keep regs <= 64) ----
    const float* as_h = ATT ? (asrc + blockIdx.y * 64) : nullptr;
    const float* ad_h = ATT ? (adst + blockIdx.y * 64) : nullptr;

    float sal0 = 0.f, sad0 = 0.f, sal1 = 0.f, sad1 = 0.f;
    int r = row0 + mrow + grp;
#pragma unroll
    for (int j = 0; j < 8; j++) {
        int col = bn0 + j * 8 + qid * 2;
        float b0 = b ? b[col] : 0.f;
        float b1 = b ? b[col + 1] : 0.f;
        float v0 = acc[j][0] + b0, v1 = acc[j][1] + b1;
        float v2 = acc[j][2] + b0, v3 = acc[j][3] + b1;
        if (RELU) {
            v0 = fmaxf(v0, 0.f); v1 = fmaxf(v1, 0.f);
            v2 = fmaxf(v2, 0.f); v3 = fmaxf(v3, 0.f);
        }
        if (ATT) {
            int c = j * 8 + qid * 2;
            float vs0 = as_h[c], vs1 = as_h[c + 1];
            float vd0 = ad_h[c], vd1 = ad_h[c + 1];
            sal0 += v0 * vs0 + v1 * vs1;
            sad0 += v0 * vd0 + v1 * vd1;
            sal1 += v2 * vs0 + v3 * vs1;
            sad1 += v2 * vd0 + v3 * vd1;
        }
        if (HALFC) {
            __half* Ch = (__half*)Cv;
            if (r < N)
                *(__half2*)&Ch[(size_t)r * KTOT + col] = __floats2half2_rn(v0, v1);
            if (r + 8 < N)
                *(__half2*)&Ch[(size_t)(r + 8) * KTOT + col] = __floats2half2_rn(v2, v3);
        } else {
            float* C = (float*)Cv;
            if (r < N)
                *(float2*)&C[(size_t)r * KTOT + col] = make_float2(v0, v1);
            if (r + 8 < N)
                *(float2*)&C[(size_t)(r + 8) * KTOT + col] = make_float2(v2, v3);
        }
    }
    if (ATT) {
#pragma unroll
        for (int off = 1; off < 4; off <<= 1) {
            sal0 += __shfl_xor_sync(0xffffffffu, sal0, off);
            sad0 += __shfl_xor_sync(0xffffffffu, sad0, off);
            sal1 += __shfl_xor_sync(0xffffffffu, sal1, off);
            sad1 += __shfl_xor_sync(0xffffffffu, sad1, off);
        }
        if (qid == 0) {
            int h = blockIdx.y;
            if (r < N)     { als[(size_t)r * 8 + h] = sal0; ald[(size_t)r * 8 + h] = sad0; }
            if (r + 8 < N) { als[(size_t)(r + 8) * 8 + h] = sal1; ald[(size_t)(r + 8) * 8 + h] = sad1; }
        }
    }
}

// ---------------- CSR build ----------------
__global__ void deg_kernel(const int* __restrict__ ei, int* __restrict__ deg, int E) {
    int i = blockIdx.x * blockDim.x + threadIdx.x;
    if (i < E) atomicAdd(&deg[ei[E + i]], 1);
}

__global__ void scan_kernel(const int* __restrict__ deg, int* __restrict__ rowstart,
                            int* __restrict__ cursor, float* __restrict__ dinv,
                            float* __restrict__ sinv, int N) {
    __shared__ int sums[1024];
    int tid = threadIdx.x;
    int CH = (N + 1023) >> 10;
    int i0 = tid * CH;
    int iend = min(i0 + CH, N);
    int s = 0;
    for (int i = i0; i < iend; i++) s += deg[i];
    sums[tid] = s;
    __syncthreads();
    for (int off = 1; off < 1024; off <<= 1) {
        int v = (tid >= off) ? sums[tid - off] : 0;
        __syncthreads();
        sums[tid] += v;
        __syncthreads();
    }
    int run = tid ? sums[tid - 1] : 0;
    for (int i = i0; i < iend; i++) {
        int d = deg[i];
        rowstart[i] = run;
        cursor[i] = run;
        dinv[i] = rsqrtf((float)d + 1.0f);
        sinv[i] = 1.0f / fmaxf((float)d, 1.0f);
        run += d;
    }
    if (tid == 1023) rowstart[N] = sums[1023];
}

__global__ void csr_fill(const int* __restrict__ ei, int* __restrict__ cursor,
                         int* __restrict__ csr_src, int E) {
    int i = blockIdx.x * blockDim.x + threadIdx.x;
    if (i >= E) return;
    int s = ei[i], d = ei[E + i];
    int pos = atomicAdd(&cursor[d], 1);
    csr_src[pos] = s;
}

// ---------------- GCN gather (fp16 table in, fp32 out) ----------------
__global__ void gcn_gather(const __half* __restrict__ tmp, const int* __restrict__ csr,
                           const int* __restrict__ rowstart, const float* __restrict__ dinv,
                           const float* __restrict__ b, float* __restrict__ h, int N) {
    int wid = (blockIdx.x * blockDim.x + threadIdx.x) >> 5;
    int lane = threadIdx.x & 31;
    if (wid >= N) return;
    int n = wid;
    float dn = dinv[n];
    float4 acc = f4mul(h4_to_f4(((const uint2*)(tmp + (size_t)n * 128))[lane]), dn * dn);
    int e = rowstart[n], e1 = rowstart[n + 1];
    for (; e + 3 < e1; e += 4) {
        int s0 = csr[e], s1 = csr[e + 1], s2 = csr[e + 2], s3 = csr[e + 3];
        float n0 = dinv[s0] * dn, n1 = dinv[s1] * dn, n2 = dinv[s2] * dn, n3 = dinv[s3] * dn;
        float4 v0 = h4_to_f4(((const uint2*)(tmp + (size_t)s0 * 128))[lane]);
        float4 v1 = h4_to_f4(((const uint2*)(tmp + (size_t)s1 * 128))[lane]);
        float4 v2 = h4_to_f4(((const uint2*)(tmp + (size_t)s2 * 128))[lane]);
        float4 v3 = h4_to_f4(((const uint2*)(tmp + (size_t)s3 * 128))[lane]);
        f4fma(acc, v0, n0); f4fma(acc, v1, n1); f4fma(acc, v2, n2); f4fma(acc, v3, n3);
    }
    for (; e < e1; e++) {
        int s0 = csr[e];
        float4 v0 = h4_to_f4(((const uint2*)(tmp + (size_t)s0 * 128))[lane]);
        f4fma(acc, v0, dinv[s0] * dn);
    }
    float4 bv = ((const float4*)b)[lane];
    f4add(acc, bv);
    acc.x = fmaxf(acc.x, 0.f); acc.y = fmaxf(acc.y, 0.f);
    acc.z = fmaxf(acc.z, 0.f); acc.w = fmaxf(acc.w, 0.f);
    ((float4*)(h + (size_t)n * 128))[lane] = acc;
}

// ---------------- SAGE gathers ----------------
__global__ void sage_gather128(const float* __restrict__ x, const int* __restrict__ csr,
                               const int* __restrict__ rowstart, const float* __restrict__ sinv,
                               float* __restrict__ out, int N) {
    int wid = (blockIdx.x * blockDim.x + threadIdx.x) >> 5;
    int lane = threadIdx.x & 31;
    if (wid >= N) return;
    int n = wid;
    float4 acc = make_float4(0.f, 0.f, 0.f, 0.f);
    int e = rowstart[n], e1 = rowstart[n + 1];
    for (; e + 3 < e1; e += 4) {
        int s0 = csr[e], s1 = csr[e + 1], s2 = csr[e + 2], s3 = csr[e + 3];
        float4 v0 = ((const float4*)(x + (size_t)s0 * 128))[lane];
        float4 v1 = ((const float4*)(x + (size_t)s1 * 128))[lane];
        float4 v2 = ((const float4*)(x + (size_t)s2 * 128))[lane];
        float4 v3 = ((const float4*)(x + (size_t)s3 * 128))[lane];
        f4add(acc, v0); f4add(acc, v1); f4add(acc, v2); f4add(acc, v3);
    }
    for (; e < e1; e++) {
        float4 v0 = ((const float4*)(x + (size_t)csr[e] * 128))[lane];
        f4add(acc, v0);
    }
    ((float4*)(out + (size_t)n * 128))[lane] = f4mul(acc, sinv[n]);
}

__global__ void sage_gather64(const float* __restrict__ x, const int* __restrict__ csr,
                              const int* __restrict__ rowstart, const float* __restrict__ sinv,
                              float* __restrict__ out, int N) {
    int wid = (blockIdx.x * blockDim.x + threadIdx.x) >> 5;
    int lane = threadIdx.x & 31;
    if (wid >= N) return;
    int n = wid;
    float2 acc = make_float2(0.f, 0.f);
    int e = rowstart[n], e1 = rowstart[n + 1];
    for (; e + 3 < e1; e += 4) {
        int s0 = csr[e], s1 = csr[e + 1], s2 = csr[e + 2], s3 = csr[e + 3];
        float2 v0 = ((const float2*)(x + (size_t)s0 * 64))[lane];
        float2 v1 = ((const float2*)(x + (size_t)s1 * 64))[lane];
        float2 v2 = ((const float2*)(x + (size_t)s2 * 64))[lane];
        float2 v3 = ((const float2*)(x + (size_t)s3 * 64))[lane];
        acc.x += v0.x + v1.x + v2.x + v3.x;
        acc.y += v0.y + v1.y + v2.y + v3.y;
    }
    for (; e < e1; e++) {
        float2 v0 = ((const float2*)(x + (size_t)csr[e] * 64))[lane];
        acc.x += v0.x; acc.y += v0.y;
    }
    float s = sinv[n];
    ((float2*)(out + (size_t)n * 64))[lane] = make_float2(acc.x * s, acc.y * s);
}

// ---------------- GAT fused (fp16 feature table + fp16 ev buffer) ----------------
__global__ void gat_fused(const int* __restrict__ csr, const int* __restrict__ rowstart,
                          const float* __restrict__ als, const float* __restrict__ ald,
                          const __half* __restrict__ gath, const float* __restrict__ gat_b,
                          __half* __restrict__ ev, float* __restrict__ gatout, int N) {
    int wid = (blockIdx.x * blockDim.x + threadIdx.x) >> 5;
    int lane = threadIdx.x & 31;
    if (wid >= N) return;
    int n = wid;
    int e0 = rowstart[n], e1 = rowstart[n + 1];

    F8 aldn = ld8(ald + (size_t)n * 8);
    F8 alsn = ld8(als + (size_t)n * 8);

    float es[8], den[8];
#pragma unroll
    for (int h = 0; h < 8; h++) {
        float l = alsn.v[h] + aldn.v[h];
        l = (l > 0.f) ? l : 0.2f * l;
        es[h] = __expf(l);
        den[h] = (lane == 0) ? es[h] : 0.f;
    }
    for (int e = e0 + lane; e < e1; e += 32) {
        F8 a = ld8(als + (size_t)csr[e] * 8);
        float t[8];
#pragma unroll
        for (int h = 0; h < 8; h++) {
            float l = a.v[h] + aldn.v[h];
            l = (l > 0.f) ? l : 0.2f * l;
            float x = __expf(l);
            den[h] += x;
            t[h] = x;
        }
        *(uint4*)(ev + (size_t)e * 8) = make_uint4(
            pack_h2(t[0], t[1]), pack_h2(t[2], t[3]),
            pack_h2(t[4], t[5]), pack_h2(t[6], t[7]));
    }
#pragma unroll
    for (int off = 16; off; off >>= 1)
#pragma unroll
        for (int h = 0; h < 8; h++)
            den[h] += __shfl_xor_sync(0xffffffffu, den[h], off);

    float rden[8];
#pragma unroll
    for (int h = 0; h < 8; h++) rden[h] = 1.0f / den[h];

    __threadfence_block();
    __syncwarp();

    int c0 = lane * 2;
    float2 acc = make_float2(0.f, 0.f);
#pragma unroll
    for (int h = 0; h < 8; h++) {
        float a = es[h] * rden[h];
        float2 g = __half22float2(*(const __half2*)(gath + (size_t)n * 512 + h * 64 + c0));
        acc.x += a * g.x; acc.y += a * g.y;
    }
    int e = e0;
    for (; e + 1 < e1; e += 2) {
        int sA = csr[e], sB = csr[e + 1];
        F8 xA = ldh8(ev + (size_t)e * 8);
        F8 xB = ldh8(ev + (size_t)(e + 1) * 8);
        const __half* grA = gath + (size_t)sA * 512 + c0;
        const __half* grB = gath + (size_t)sB * 512 + c0;
#pragma unroll
        for (int h = 0; h < 8; h++) {
            float aA = xA.v[h] * rden[h];
            float aB = xB.v[h] * rden[h];
            float2 gA = __half22float2(*(const __half2*)(grA + h * 64));
            float2 gB = __half22float2(*(const __half2*)(grB + h * 64));
            acc.x += aA * gA.x + aB * gB.x;
            acc.y += aA * gA.y + aB * gB.y;
        }
    }
    if (e < e1) {
        int s = csr[e];
        F8 x = ldh8(ev + (size_t)e * 8);
        const __half* gr = gath + (size_t)s * 512 + c0;
#pragma unroll
        for (int h = 0; h < 8; h++) {
            float a = x.v[h] * rden[h];
            float2 g = __half22float2(*(const __half2*)(gr + h * 64));
            acc.x += a * g.x; acc.y += a * g.y;
        }
    }
    gatout[(size_t)n * 64 + c0]     = acc.x * 0.125f + gat_b[c0];
    gatout[(size_t)n * 64 + c0 + 1] = acc.y * 0.125f + gat_b[c0 + 1];
}

// ---------------- pooling ----------------
__global__ void pool_kernel(const float* __restrict__ gatout, const float* __restrict__ s2,
                            const int* __restrict__ batch, float* __restrict__ pooled,
                            float* __restrict__ cnt, int N) {
    int c = threadIdx.x;
    int n0 = blockIdx.x * 32;
    if (n0 >= N) return;
    int nend = min(n0 + 32, N);
    int cur = batch[n0];
    float acc = 0.f, cc = 0.f;
    for (int n = n0; n < nend; n++) {
        int g = batch[n];
        if (g != cur) {
            atomicAdd(&pooled[cur * 128 + c], acc);
            if (c == 0) atomicAdd(&cnt[cur], cc);
            acc = 0.f; cc = 0.f; cur = g;
        }
        acc += (c < 64) ? gatout[(size_t)n * 64 + c] : s2[(size_t)n * 64 + (c - 64)];
        cc += 1.f;
    }
    atomicAdd(&pooled[cur * 128 + c], acc);
    if (c == 0) atomicAdd(&cnt[cur], cc);
}

__global__ void final_kernel(const float* __restrict__ pooled, const float* __restrict__ cnt,
                             const float* __restrict__ projw, const float* __restrict__ projb,
                             float* __restrict__ out) {
    int g = blockIdx.x, c = threadIdx.x;
    float inv = 1.0f / fmaxf(cnt[g], 1.0f);
    float acc = 0.f;
#pragma unroll 8
    for (int k = 0; k < 128; k++)
        acc += pooled[g * 128 + k] * projw[k * 64 + c];
    out[g * 64 + c] = acc * inv + projb[c];
}

// ---------------- launch ----------------
extern "C" void kernel_launch(void* const* d_in, const int* in_sizes, int n_in,
                              void* d_out, int out_size) {
    const float* x       = (const float*)d_in[0];
    const int*   ei      = (const int*)d_in[1];
    const int*   batch   = (const int*)d_in[2];
    const float* gcn_w0  = (const float*)d_in[3];
    const float* gcn_b0  = (const float*)d_in[4];
    const float* gcn_w1  = (const float*)d_in[5];
    const float* gcn_b1  = (const float*)d_in[6];
    const float* gat_w   = (const float*)d_in[7];
    const float* att_src = (const float*)d_in[8];
    const float* att_dst = (const float*)d_in[9];
    const float* gat_b   = (const float*)d_in[10];
    const float* s1wl    = (const float*)d_in[11];
    const float* s1wr    = (const float*)d_in[12];
    const float* s1b     = (const float*)d_in[13];
    const float* s2wl    = (const float*)d_in[14];
    const float* s2wr    = (const float*)d_in[15];
    const float* s2b     = (const float*)d_in[16];
    const float* projw   = (const float*)d_in[17];
    const float* projb   = (const float*)d_in[18];

    const int N = in_sizes[0] / DIN;
    const int E = in_sizes[1] / 2;
    float* out = (float*)d_out;

    int *deg, *rowstart, *cursor, *csr;
    float *dinv, *sinv, *h0, *h1, *als, *ald, *gatout,
          *agg, *s1, *agg2, *s2, *pooled, *cnt;
    __half *tmp, *gath, *ev;
    cudaGetSymbolAddress((void**)&deg, g_deg);
    cudaGetSymbolAddress((void**)&rowstart, g_rowstart);
    cudaGetSymbolAddress((void**)&cursor, g_cursor);
    cudaGetSymbolAddress((void**)&csr, g_csr_src);
    cudaGetSymbolAddress((void**)&dinv, g_dinv);
    cudaGetSymbolAddress((void**)&sinv, g_sinv);
    cudaGetSymbolAddress((void**)&tmp, g_tmp);
    cudaGetSymbolAddress((void**)&h0, g_h0);
    cudaGetSymbolAddress((void**)&h1, g_h1);
    cudaGetSymbolAddress((void**)&gath, g_gath);
    cudaGetSymbolAddress((void**)&als, g_als);
    cudaGetSymbolAddress((void**)&ald, g_ald);
    cudaGetSymbolAddress((void**)&ev, g_ev);
    cudaGetSymbolAddress((void**)&gatout, g_gatout);
    cudaGetSymbolAddress((void**)&agg, g_agg);
    cudaGetSymbolAddress((void**)&s1, g_s1);
    cudaGetSymbolAddress((void**)&agg2, g_agg2);
    cudaGetSymbolAddress((void**)&s2, g_s2);
    cudaGetSymbolAddress((void**)&pooled, g_pooled);
    cudaGetSymbolAddress((void**)&cnt, g_cnt);

    static cudaStream_t sideq = nullptr;
    static cudaEvent_t evA = nullptr, evB = nullptr, evC = nullptr, evD = nullptr;
    if (!sideq) {
        cudaStreamCreateWithFlags(&sideq, cudaStreamNonBlocking);
        cudaEventCreateWithFlags(&evA, cudaEventDisableTiming);
        cudaEventCreateWithFlags(&evB, cudaEventDisableTiming);
        cudaEventCreateWithFlags(&evC, cudaEventDisableTiming);
        cudaEventCreateWithFlags(&evD, cudaEventDisableTiming);
    }

    const int T = 256;
    int nodeWarpBlocks = (N * 32 + T - 1) / T;
    int gRows = (N + 127) / 128;

    // ---- fork: CSR build on side stream, GCN0 GEMM on main ----
    cudaEventRecord(evA, 0);
    cudaStreamWaitEvent(sideq, evA, 0);
    cudaMemsetAsync(deg, 0, N * sizeof(int), sideq);
    deg_kernel<<<(E + T - 1) / T, T, 0, sideq>>>(ei, deg, E);
    scan_kernel<<<1, 1024, 0, sideq>>>(deg, rowstart, cursor, dinv, sinv, N);
    csr_fill<<<(E + T - 1) / T, T, 0, sideq>>>(ei, cursor, csr, E);
    cudaEventRecord(evB, sideq);

    gemm_f16<128, 128, false, false, false, true><<<dim3(gRows, 2), 256>>>(
        x, gcn_w0, nullptr, nullptr, nullptr, tmp, N, nullptr, nullptr, nullptr, nullptr);

    cudaStreamWaitEvent(0, evB, 0);
    gcn_gather<<<nodeWarpBlocks, T>>>(tmp, csr, rowstart, dinv, gcn_b0, h0, N);

    gemm_f16<128, 128, false, false, false, true><<<dim3(gRows, 2), 256>>>(
        h0, gcn_w1, nullptr, nullptr, nullptr, tmp, N, nullptr, nullptr, nullptr, nullptr);
    gcn_gather<<<nodeWarpBlocks, T>>>(tmp, csr, rowstart, dinv, gcn_b1, h1, N);

    // ---- fork: SAGE chain on side stream, GAT on main ----
    cudaEventRecord(evC, 0);
    cudaStreamWaitEvent(sideq, evC, 0);
    sage_gather128<<<nodeWarpBlocks, T, 0, sideq>>>(h1, csr, rowstart, sinv, agg, N);
    gemm_f16<128, 64, true, true, false, false><<<dim3(gRows, 1), 256, 0, sideq>>>(
        agg, s1wl, h1, s1wr, s1b, s1, N, nullptr, nullptr, nullptr, nullptr);
    sage_gather64<<<nodeWarpBlocks, T, 0, sideq>>>(s1, csr, rowstart, sinv, agg2, N);
    gemm_f16<64, 64, true, false, false, false><<<dim3(gRows, 1), 256, 0, sideq>>>(
        agg2, s2wl, s1, s2wr, s2b, s2, N, nullptr, nullptr, nullptr, nullptr);
    cudaEventRecord(evD, sideq);

    gemm_f16<128, 512, false, false, true, true><<<dim3(gRows, 8), 256>>>(
        h1, gat_w, nullptr, nullptr, nullptr, gath, N, att_src, att_dst, als, ald);
    gat_fused<<<nodeWarpBlocks, T>>>(csr, rowstart, als, ald, gath, gat_b, ev, gatout, N);

    // ---- join, pool, project ----
    cudaMemsetAsync(pooled, 0, GG * 128 * sizeof(float));
    cudaMemsetAsync(cnt, 0, GG * sizeof(float));
    cudaStreamWaitEvent(0, evD, 0);
    pool_kernel<<<(N + 31) / 32, 128>>>(gatout, s2, batch, pooled, cnt, N);
    final_kernel<<<GG, 64>>>(pooled, cnt, projw, projb, out);
}

// round 14
// speedup vs baseline: 1.0667x; 1.0667x over previous
#include <cuda_runtime.h>
#include <cuda_fp16.h>
#include <math.h>
#include <stdint.h>

#define NN 20000
#define EE 320000
#define DIN 128
#define DHID 128
#define DOUT 64
#define HEADS 8
#define GG 64

// fp16 weight scratch offsets
#define WO_GCN0   0
#define WO_GCN1   16384
#define WO_GATW   32768
#define WO_S1WL   98304
#define WO_S1WR   106496
#define WO_S2WL   114688
#define WO_S2WR   118784
#define W_TOTAL   122880

// ---------------- scratch ----------------
__device__ int    g_deg[NN];
__device__ int    g_rowstart[NN + 1];
__device__ int    g_cursor[NN];
__device__ int    g_csr_src[EE];
__device__ float  g_dinv[NN];
__device__ float  g_sinv[NN];
__device__ __half g_wh[W_TOTAL];               // fp16 weights (converted once)
__device__ __half g_tmp[NN * DHID];            // fp16 GCN pre-agg table
__device__ __half g_h0[NN * DHID];             // fp16 features
__device__ __half g_h1[NN * DHID];
__device__ __half g_gath[NN * HEADS * DOUT];
__device__ float  g_als[NN * HEADS];
__device__ float  g_ald[NN * HEADS];
__device__ __half g_ev[EE * HEADS];
__device__ float  g_gatout[NN * DOUT];
__device__ __half g_agg[NN * DHID];
__device__ __half g_s1[NN * DOUT];
__device__ __half g_agg2[NN * DOUT];
__device__ float  g_s2[NN * DOUT];
__device__ float  g_pooled[GG * 128];
__device__ float  g_cnt[GG];

// ---------------- helpers ----------------
__device__ __forceinline__ float4 f4mul(float4 a, float s) {
    return make_float4(a.x * s, a.y * s, a.z * s, a.w * s);
}
__device__ __forceinline__ void f4fma(float4& acc, float4 a, float s) {
    acc.x += a.x * s; acc.y += a.y * s; acc.z += a.z * s; acc.w += a.w * s;
}
__device__ __forceinline__ void f4add(float4& acc, float4 a) {
    acc.x += a.x; acc.y += a.y; acc.z += a.z; acc.w += a.w;
}
struct F8 { float v[8]; };
__device__ __forceinline__ F8 ld8(const float* p) {
    F8 r;
    float4 a = *(const float4*)p;
    float4 b = *(const float4*)(p + 4);
    r.v[0]=a.x; r.v[1]=a.y; r.v[2]=a.z; r.v[3]=a.w;
    r.v[4]=b.x; r.v[5]=b.y; r.v[6]=b.z; r.v[7]=b.w;
    return r;
}
__device__ __forceinline__ F8 ldh8(const __half* p) {
    uint4 u = *(const uint4*)p;
    F8 r;
    float2 f;
    f = __half22float2(*(__half2*)&u.x); r.v[0]=f.x; r.v[1]=f.y;
    f = __half22float2(*(__half2*)&u.y); r.v[2]=f.x; r.v[3]=f.y;
    f = __half22float2(*(__half2*)&u.z); r.v[4]=f.x; r.v[5]=f.y;
    f = __half22float2(*(__half2*)&u.w); r.v[6]=f.x; r.v[7]=f.y;
    return r;
}
__device__ __forceinline__ uint32_t pack_h2(float a, float b) {
    __half2 h = __floats2half2_rn(a, b);
    return *(uint32_t*)&h;
}
__device__ __forceinline__ uint4 cvt8(float4 a, float4 b) {
    return make_uint4(pack_h2(a.x, a.y), pack_h2(a.z, a.w),
                      pack_h2(b.x, b.y), pack_h2(b.z, b.w));
}
__device__ __forceinline__ float4 h4_to_f4(uint2 v) {
    float2 fa = __half22float2(*(__half2*)&v.x);
    float2 fb = __half22float2(*(__half2*)&v.y);
    return make_float4(fa.x, fa.y, fb.x, fb.y);
}

__device__ __forceinline__ void ldm_x4(uint32_t& r0, uint32_t& r1, uint32_t& r2, uint32_t& r3,
                                       uint32_t addr) {
    asm volatile("ldmatrix.sync.aligned.m8n8.x4.shared.b16 {%0,%1,%2,%3}, [%4];\n"
                 : "=r"(r0), "=r"(r1), "=r"(r2), "=r"(r3) : "r"(addr));
}
__device__ __forceinline__ void ldm_x4_t(uint32_t& r0, uint32_t& r1, uint32_t& r2, uint32_t& r3,
                                         uint32_t addr) {
    asm volatile("ldmatrix.sync.aligned.m8n8.x4.trans.shared.b16 {%0,%1,%2,%3}, [%4];\n"
                 : "=r"(r0), "=r"(r1), "=r"(r2), "=r"(r3) : "r"(addr));
}
__device__ __forceinline__ void mma_f16(float* d, uint32_t a0, uint32_t a1, uint32_t a2,
                                        uint32_t a3, uint32_t b0, uint32_t b1) {
    asm volatile(
        "mma.sync.aligned.m16n8k16.row.col.f32.f16.f16.f32 "
        "{%0,%1,%2,%3}, {%4,%5,%6,%7}, {%8,%9}, {%0,%1,%2,%3};\n"
        : "+f"(d[0]), "+f"(d[1]), "+f"(d[2]), "+f"(d[3])
        : "r"(a0), "r"(a1), "r"(a2), "r"(a3), "r"(b0), "r"(b1));
}

// ---------------- weight pre-conversion ----------------
__global__ void cvt_weights(const float* __restrict__ w0, const float* __restrict__ w1,
                            const float* __restrict__ gatw,
                            const float* __restrict__ s1wl, const float* __restrict__ s1wr,
                            const float* __restrict__ s2wl, const float* __restrict__ s2wr,
                            __half* __restrict__ out) {
    int i = blockIdx.x * blockDim.x + threadIdx.x;
    if (i >= W_TOTAL) return;
    const float* src; int off;
    if      (i < WO_GCN1) { src = w0;   off = WO_GCN0; }
    else if (i < WO_GATW) { src = w1;   off = WO_GCN1; }
    else if (i < WO_S1WL) { src = gatw; off = WO_GATW; }
    else if (i < WO_S1WR) { src = s1wl; off = WO_S1WL; }
    else if (i < WO_S2WL) { src = s1wr; off = WO_S1WR; }
    else if (i < WO_S2WR) { src = s2wl; off = WO_S2WL; }
    else                  { src = s2wr; off = WO_S2WR; }
    out[i] = __float2half(src[i - off]);
}

// ---------------- fp16 tensor-core GEMM, BM=128 x BN=64, 8 warps ----------------
// C = A1@W1 (+A2@W2) (+b) (relu?) (attention logits if ATT; fp16 C if HALFC)
// W is fp16 (pre-converted). A fp16 if AHALF, else fp32 with cvt at staging.
template<int M, int KTOT, bool DUAL, bool RELU, bool ATT, bool HALFC, bool AHALF>
__global__ void __launch_bounds__(256, 4)
gemm_f16(const void* __restrict__ A1v, const __half* __restrict__ W1,
         const void* __restrict__ A2v, const __half* __restrict__ W2,
         const float* __restrict__ b, void* __restrict__ Cv, int N,
         const float* __restrict__ asrc, const float* __restrict__ adst,
         float* __restrict__ als, float* __restrict__ ald) {
    constexpr int ASTRH = M + 8;
    constexpr int BSTRH = 72;
    __shared__ __align__(16) __half As[128 * ASTRH];
    __shared__ __align__(16) __half Bs[32 * BSTRH];
    int tid = threadIdx.x;
    int warp = tid >> 5, lane = tid & 31;
    int grp = lane >> 2, qid = lane & 3;
    int row0 = blockIdx.x * 128;
    int bn0 = blockIdx.y * 64;
    int mrow = warp * 16;

    float acc[8][4];
#pragma unroll
    for (int j = 0; j < 8; j++)
#pragma unroll
        for (int c = 0; c < 4; c++) acc[j][c] = 0.f;

    int lt = lane >> 3, lr = lane & 7;
    uint32_t a_base = (uint32_t)__cvta_generic_to_shared(
        &As[(mrow + ((lt & 1) << 3) + lr) * ASTRH + ((lt >> 1) << 3)]);
    uint32_t b_base = (uint32_t)__cvta_generic_to_shared(
        &Bs[(((lt & 1) << 3) + lr) * BSTRH + ((lt >> 1) << 3)]);

    auto stage_a = [&](const void* Av) {
        // 128 rows x (M/8) segments of 8 elements; 256 threads
#pragma unroll
        for (int i = 0; i < M / 16; i++) {
            int q = tid + i * 256;
            int row = q / (M / 8), seg = q % (M / 8);
            uint4 hv;
            if (row0 + row < N) {
                if (AHALF) {
                    const __half* A = (const __half*)Av;
                    hv = *(const uint4*)(A + (size_t)(row0 + row) * M + seg * 8);
                } else {
                    const float* A = (const float*)Av;
                    const float* src = A + (size_t)(row0 + row) * M + seg * 8;
                    hv = cvt8(*(const float4*)src, *(const float4*)(src + 4));
                }
            } else {
                hv = make_uint4(0u, 0u, 0u, 0u);
            }
            *(uint4*)&As[row * ASTRH + seg * 8] = hv;
        }
    };
    auto stage_b = [&](const __half* W, int kc) {
        // 32 k-rows x 8 segments of 8 halves; one per thread
        int r = tid >> 3, seg = tid & 7;
        *(uint4*)&Bs[r * BSTRH + seg * 8] =
            *(const uint4*)(W + (size_t)(kc + r) * KTOT + bn0 + seg * 8);
    };
    auto mma_chunk = [&](int kc) {
#pragma unroll
        for (int ks2 = 0; ks2 < 2; ks2++) {
            uint32_t a0, a1, a2, a3;
            ldm_x4(a0, a1, a2, a3, a_base + (uint32_t)(kc + ks2 * 16) * 2);
#pragma unroll
            for (int jp = 0; jp < 4; jp++) {
                uint32_t b0, b1, b2, b3;
                ldm_x4_t(b0, b1, b2, b3,
                         b_base + (uint32_t)(ks2 * 16 * BSTRH + jp * 16) * 2);
                mma_f16(acc[jp * 2],     a0, a1, a2, a3, b0, b1);
                mma_f16(acc[jp * 2 + 1], a0, a1, a2, a3, b2, b3);
            }
        }
    };

    stage_a(A1v);
#pragma unroll
    for (int kc = 0; kc < M; kc += 32) {
        __syncthreads();
        stage_b(W1, kc);
        __syncthreads();
        mma_chunk(kc);
    }
    if (DUAL) {
        __syncthreads();
        stage_a(A2v);
#pragma unroll
        for (int kc = 0; kc < M; kc += 32) {
            __syncthreads();
            stage_b(W2, kc);
            __syncthreads();
            mma_chunk(kc);
        }
    }

    // ---- epilogue ----
    const float* as_h = ATT ? (asrc + blockIdx.y * 64) : nullptr;
    const float* ad_h = ATT ? (adst + blockIdx.y * 64) : nullptr;

    float sal0 = 0.f, sad0 = 0.f, sal1 = 0.f, sad1 = 0.f;
    int r = row0 + mrow + grp;
#pragma unroll
    for (int j = 0; j < 8; j++) {
        int col = bn0 + j * 8 + qid * 2;
        float b0 = b ? b[col] : 0.f;
        float b1 = b ? b[col + 1] : 0.f;
        float v0 = acc[j][0] + b0, v1 = acc[j][1] + b1;
        float v2 = acc[j][2] + b0, v3 = acc[j][3] + b1;
        if (RELU) {
            v0 = fmaxf(v0, 0.f); v1 = fmaxf(v1, 0.f);
            v2 = fmaxf(v2, 0.f); v3 = fmaxf(v3, 0.f);
        }
        if (ATT) {
            int c = j * 8 + qid * 2;
            float vs0 = as_h[c], vs1 = as_h[c + 1];
            float vd0 = ad_h[c], vd1 = ad_h[c + 1];
            sal0 += v0 * vs0 + v1 * vs1;
            sad0 += v0 * vd0 + v1 * vd1;
            sal1 += v2 * vs0 + v3 * vs1;
            sad1 += v2 * vd0 + v3 * vd1;
        }
        if (HALFC) {
            __half* Ch = (__half*)Cv;
            if (r < N)
                *(__half2*)&Ch[(size_t)r * KTOT + col] = __floats2half2_rn(v0, v1);
            if (r + 8 < N)
                *(__half2*)&Ch[(size_t)(r + 8) * KTOT + col] = __floats2half2_rn(v2, v3);
        } else {
            float* C = (float*)Cv;
            if (r < N)
                *(float2*)&C[(size_t)r * KTOT + col] = make_float2(v0, v1);
            if (r + 8 < N)
                *(float2*)&C[(size_t)(r + 8) * KTOT + col] = make_float2(v2, v3);
        }
    }
    if (ATT) {
#pragma unroll
        for (int off = 1; off < 4; off <<= 1) {
            sal0 += __shfl_xor_sync(0xffffffffu, sal0, off);
            sad0 += __shfl_xor_sync(0xffffffffu, sad0, off);
            sal1 += __shfl_xor_sync(0xffffffffu, sal1, off);
            sad1 += __shfl_xor_sync(0xffffffffu, sad1, off);
        }
        if (qid == 0) {
            int h = blockIdx.y;
            if (r < N)     { als[(size_t)r * 8 + h] = sal0; ald[(size_t)r * 8 + h] = sad0; }
            if (r + 8 < N) { als[(size_t)(r + 8) * 8 + h] = sal1; ald[(size_t)(r + 8) * 8 + h] = sad1; }
        }
    }
}

// ---------------- CSR build ----------------
__global__ void deg_kernel(const int* __restrict__ ei, int* __restrict__ deg, int E) {
    int i = blockIdx.x * blockDim.x + threadIdx.x;
    if (i < E) atomicAdd(&deg[ei[E + i]], 1);
}

__global__ void scan_kernel(const int* __restrict__ deg, int* __restrict__ rowstart,
                            int* __restrict__ cursor, float* __restrict__ dinv,
                            float* __restrict__ sinv, int N) {
    __shared__ int sums[1024];
    int tid = threadIdx.x;
    int CH = (N + 1023) >> 10;
    int i0 = tid * CH;
    int iend = min(i0 + CH, N);
    int s = 0;
    for (int i = i0; i < iend; i++) s += deg[i];
    sums[tid] = s;
    __syncthreads();
    for (int off = 1; off < 1024; off <<= 1) {
        int v = (tid >= off) ? sums[tid - off] : 0;
        __syncthreads();
        sums[tid] += v;
        __syncthreads();
    }
    int run = tid ? sums[tid - 1] : 0;
    for (int i = i0; i < iend; i++) {
        int d = deg[i];
        rowstart[i] = run;
        cursor[i] = run;
        dinv[i] = rsqrtf((float)d + 1.0f);
        sinv[i] = 1.0f / fmaxf((float)d, 1.0f);
        run += d;
    }
    if (tid == 1023) rowstart[N] = sums[1023];
}

__global__ void csr_fill(const int* __restrict__ ei, int* __restrict__ cursor,
                         int* __restrict__ csr_src, int E) {
    int i = blockIdx.x * blockDim.x + threadIdx.x;
    if (i >= E) return;
    int s = ei[i], d = ei[E + i];
    int pos = atomicAdd(&cursor[d], 1);
    csr_src[pos] = s;
}

// ---------------- GCN gather (fp16 table in, fp16 out) ----------------
__global__ void gcn_gather(const __half* __restrict__ tmp, const int* __restrict__ csr,
                           const int* __restrict__ rowstart, const float* __restrict__ dinv,
                           const float* __restrict__ b, __half* __restrict__ h, int N) {
    int wid = (blockIdx.x * blockDim.x + threadIdx.x) >> 5;
    int lane = threadIdx.x & 31;
    if (wid >= N) return;
    int n = wid;
    float dn = dinv[n];
    float4 acc = f4mul(h4_to_f4(((const uint2*)(tmp + (size_t)n * 128))[lane]), dn * dn);
    int e = rowstart[n], e1 = rowstart[n + 1];
    for (; e + 3 < e1; e += 4) {
        int s0 = csr[e], s1 = csr[e + 1], s2 = csr[e + 2], s3 = csr[e + 3];
        float n0 = dinv[s0] * dn, n1 = dinv[s1] * dn, n2 = dinv[s2] * dn, n3 = dinv[s3] * dn;
        float4 v0 = h4_to_f4(((const uint2*)(tmp + (size_t)s0 * 128))[lane]);
        float4 v1 = h4_to_f4(((const uint2*)(tmp + (size_t)s1 * 128))[lane]);
        float4 v2 = h4_to_f4(((const uint2*)(tmp + (size_t)s2 * 128))[lane]);
        float4 v3 = h4_to_f4(((const uint2*)(tmp + (size_t)s3 * 128))[lane]);
        f4fma(acc, v0, n0); f4fma(acc, v1, n1); f4fma(acc, v2, n2); f4fma(acc, v3, n3);
    }
    for (; e < e1; e++) {
        int s0 = csr[e];
        float4 v0 = h4_to_f4(((const uint2*)(tmp + (size_t)s0 * 128))[lane]);
        f4fma(acc, v0, dinv[s0] * dn);
    }
    float4 bv = ((const float4*)b)[lane];
    f4add(acc, bv);
    acc.x = fmaxf(acc.x, 0.f); acc.y = fmaxf(acc.y, 0.f);
    acc.z = fmaxf(acc.z, 0.f); acc.w = fmaxf(acc.w, 0.f);
    ((uint2*)(h + (size_t)n * 128))[lane] =
        make_uint2(pack_h2(acc.x, acc.y), pack_h2(acc.z, acc.w));
}

// ---------------- SAGE gathers (fp16 in/out) ----------------
__global__ void sage_gather128(const __half* __restrict__ x, const int* __restrict__ csr,
                               const int* __restrict__ rowstart, const float* __restrict__ sinv,
                               __half* __restrict__ out, int N) {
    int wid = (blockIdx.x * blockDim.x + threadIdx.x) >> 5;
    int lane = threadIdx.x & 31;
    if (wid >= N) return;
    int n = wid;
    float4 acc = make_float4(0.f, 0.f, 0.f, 0.f);
    int e = rowstart[n], e1 = rowstart[n + 1];
    for (; e + 3 < e1; e += 4) {
        int s0 = csr[e], s1 = csr[e + 1], s2 = csr[e + 2], s3 = csr[e + 3];
        float4 v0 = h4_to_f4(((const uint2*)(x + (size_t)s0 * 128))[lane]);
        float4 v1 = h4_to_f4(((const uint2*)(x + (size_t)s1 * 128))[lane]);
        float4 v2 = h4_to_f4(((const uint2*)(x + (size_t)s2 * 128))[lane]);
        float4 v3 = h4_to_f4(((const uint2*)(x + (size_t)s3 * 128))[lane]);
        f4add(acc, v0); f4add(acc, v1); f4add(acc, v2); f4add(acc, v3);
    }
    for (; e < e1; e++) {
        float4 v0 = h4_to_f4(((const uint2*)(x + (size_t)csr[e] * 128))[lane]);
        f4add(acc, v0);
    }
    float s = sinv[n];
    ((uint2*)(out + (size_t)n * 128))[lane] =
        make_uint2(pack_h2(acc.x * s, acc.y * s), pack_h2(acc.z * s, acc.w * s));
}

__global__ void sage_gather64(const __half* __restrict__ x, const int* __restrict__ csr,
                              const int* __restrict__ rowstart, const float* __restrict__ sinv,
                              __half* __restrict__ out, int N) {
    int wid = (blockIdx.x * blockDim.x + threadIdx.x) >> 5;
    int lane = threadIdx.x & 31;
    if (wid >= N) return;
    int n = wid;
    float2 acc = make_float2(0.f, 0.f);
    int e = rowstart[n], e1 = rowstart[n + 1];
    for (; e + 3 < e1; e += 4) {
        int s0 = csr[e], s1 = csr[e + 1], s2 = csr[e + 2], s3 = csr[e + 3];
        float2 v0 = __half22float2(((const __half2*)(x + (size_t)s0 * 64))[lane]);
        float2 v1 = __half22float2(((const __half2*)(x + (size_t)s1 * 64))[lane]);
        float2 v2 = __half22float2(((const __half2*)(x + (size_t)s2 * 64))[lane]);
        float2 v3 = __half22float2(((const __half2*)(x + (size_t)s3 * 64))[lane]);
        acc.x += v0.x + v1.x + v2.x + v3.x;
        acc.y += v0.y + v1.y + v2.y + v3.y;
    }
    for (; e < e1; e++) {
        float2 v0 = __half22float2(((const __half2*)(x + (size_t)csr[e] * 64))[lane]);
        acc.x += v0.x; acc.y += v0.y;
    }
    float s = sinv[n];
    ((__half2*)(out + (size_t)n * 64))[lane] = __floats2half2_rn(acc.x * s, acc.y * s);
}

// ---------------- GAT fused ----------------
__global__ void gat_fused(const int* __restrict__ csr, const int* __restrict__ rowstart,
                          const float* __restrict__ als, const float* __restrict__ ald,
                          const __half* __restrict__ gath, const float* __restrict__ gat_b,
                          __half* __restrict__ ev, float* __restrict__ gatout, int N) {
    int wid = (blockIdx.x * blockDim.x + threadIdx.x) >> 5;
    int lane = threadIdx.x & 31;
    if (wid >= N) return;
    int n = wid;
    int e0 = rowstart[n], e1 = rowstart[n + 1];

    F8 aldn = ld8(ald + (size_t)n * 8);
    F8 alsn = ld8(als + (size_t)n * 8);

    float es[8], den[8];
#pragma unroll
    for (int h = 0; h < 8; h++) {
        float l = alsn.v[h] + aldn.v[h];
        l = (l > 0.f) ? l : 0.2f * l;
        es[h] = __expf(l);
        den[h] = (lane == 0) ? es[h] : 0.f;
    }
    for (int e = e0 + lane; e < e1; e += 32) {
        F8 a = ld8(als + (size_t)csr[e] * 8);
        float t[8];
#pragma unroll
        for (int h = 0; h < 8; h++) {
            float l = a.v[h] + aldn.v[h];
            l = (l > 0.f) ? l : 0.2f * l;
            float x = __expf(l);
            den[h] += x;
            t[h] = x;
        }
        *(uint4*)(ev + (size_t)e * 8) = make_uint4(
            pack_h2(t[0], t[1]), pack_h2(t[2], t[3]),
            pack_h2(t[4], t[5]), pack_h2(t[6], t[7]));
    }
#pragma unroll
    for (int off = 16; off; off >>= 1)
#pragma unroll
        for (int h = 0; h < 8; h++)
            den[h] += __shfl_xor_sync(0xffffffffu, den[h], off);

    float rden[8];
#pragma unroll
    for (int h = 0; h < 8; h++) rden[h] = 1.0f / den[h];

    __threadfence_block();
    __syncwarp();

    int c0 = lane * 2;
    float2 acc = make_float2(0.f, 0.f);
#pragma unroll
    for (int h = 0; h < 8; h++) {
        float a = es[h] * rden[h];
        float2 g = __half22float2(*(const __half2*)(gath + (size_t)n * 512 + h * 64 + c0));
        acc.x += a * g.x; acc.y += a * g.y;
    }
    int e = e0;
    for (; e + 1 < e1; e += 2) {
        int sA = csr[e], sB = csr[e + 1];
        F8 xA = ldh8(ev + (size_t)e * 8);
        F8 xB = ldh8(ev + (size_t)(e + 1) * 8);
        const __half* grA = gath + (size_t)sA * 512 + c0;
        const __half* grB = gath + (size_t)sB * 512 + c0;
#pragma unroll
        for (int h = 0; h < 8; h++) {
            float aA = xA.v[h] * rden[h];
            float aB = xB.v[h] * rden[h];
            float2 gA = __half22float2(*(const __half2*)(grA + h * 64));
            float2 gB = __half22float2(*(const __half2*)(grB + h * 64));
            acc.x += aA * gA.x + aB * gB.x;
            acc.y += aA * gA.y + aB * gB.y;
        }
    }
    if (e < e1) {
        int s = csr[e];
        F8 x = ldh8(ev + (size_t)e * 8);
        const __half* gr = gath + (size_t)s * 512 + c0;
#pragma unroll
        for (int h = 0; h < 8; h++) {
            float a = x.v[h] * rden[h];
            float2 g = __half22float2(*(const __half2*)(gr + h * 64));
            acc.x += a * g.x; acc.y += a * g.y;
        }
    }
    gatout[(size_t)n * 64 + c0]     = acc.x * 0.125f + gat_b[c0];
    gatout[(size_t)n * 64 + c0 + 1] = acc.y * 0.125f + gat_b[c0 + 1];
}

// ---------------- pooling ----------------
__global__ void pool_kernel(const float* __restrict__ gatout, const float* __restrict__ s2,
                            const int* __restrict__ batch, float* __restrict__ pooled,
                            float* __restrict__ cnt, int N) {
    int c = threadIdx.x;
    int n0 = blockIdx.x * 32;
    if (n0 >= N) return;
    int nend = min(n0 + 32, N);
    int cur = batch[n0];
    float acc = 0.f, cc = 0.f;
    for (int n = n0; n < nend; n++) {
        int g = batch[n];
        if (g != cur) {
            atomicAdd(&pooled[cur * 128 + c], acc);
            if (c == 0) atomicAdd(&cnt[cur], cc);
            acc = 0.f; cc = 0.f; cur = g;
        }
        acc += (c < 64) ? gatout[(size_t)n * 64 + c] : s2[(size_t)n * 64 + (c - 64)];
        cc += 1.f;
    }
    atomicAdd(&pooled[cur * 128 + c], acc);
    if (c == 0) atomicAdd(&cnt[cur], cc);
}

__global__ void final_kernel(const float* __restrict__ pooled, const float* __restrict__ cnt,
                             const float* __restrict__ projw, const float* __restrict__ projb,
                             float* __restrict__ out) {
    int g = blockIdx.x, c = threadIdx.x;
    float inv = 1.0f / fmaxf(cnt[g], 1.0f);
    float acc = 0.f;
#pragma unroll 8
    for (int k = 0; k < 128; k++)
        acc += pooled[g * 128 + k] * projw[k * 64 + c];
    out[g * 64 + c] = acc * inv + projb[c];
}

// ---------------- launch ----------------
extern "C" void kernel_launch(void* const* d_in, const int* in_sizes, int n_in,
                              void* d_out, int out_size) {
    const float* x       = (const float*)d_in[0];
    const int*   ei      = (const int*)d_in[1];
    const int*   batch   = (const int*)d_in[2];
    const float* gcn_w0  = (const float*)d_in[3];
    const float* gcn_b0  = (const float*)d_in[4];
    const float* gcn_w1  = (const float*)d_in[5];
    const float* gcn_b1  = (const float*)d_in[6];
    const float* gat_w   = (const float*)d_in[7];
    const float* att_src = (const float*)d_in[8];
    const float* att_dst = (const float*)d_in[9];
    const float* gat_b   = (const float*)d_in[10];
    const float* s1wl    = (const float*)d_in[11];
    const float* s1wr    = (const float*)d_in[12];
    const float* s1b     = (const float*)d_in[13];
    const float* s2wl    = (const float*)d_in[14];
    const float* s2wr    = (const float*)d_in[15];
    const float* s2b     = (const float*)d_in[16];
    const float* projw   = (const float*)d_in[17];
    const float* projb   = (const float*)d_in[18];

    const int N = in_sizes[0] / DIN;
    const int E = in_sizes[1] / 2;
    float* out = (float*)d_out;

    int *deg, *rowstart, *cursor, *csr;
    float *dinv, *sinv, *als, *ald, *gatout, *s2, *pooled, *cnt;
    __half *wh, *tmp, *h0, *h1, *gath, *ev, *agg, *s1, *agg2;
    cudaGetSymbolAddress((void**)&deg, g_deg);
    cudaGetSymbolAddress((void**)&rowstart, g_rowstart);
    cudaGetSymbolAddress((void**)&cursor, g_cursor);
    cudaGetSymbolAddress((void**)&csr, g_csr_src);
    cudaGetSymbolAddress((void**)&dinv, g_dinv);
    cudaGetSymbolAddress((void**)&sinv, g_sinv);
    cudaGetSymbolAddress((void**)&wh, g_wh);
    cudaGetSymbolAddress((void**)&tmp, g_tmp);
    cudaGetSymbolAddress((void**)&h0, g_h0);
    cudaGetSymbolAddress((void**)&h1, g_h1);
    cudaGetSymbolAddress((void**)&gath, g_gath);
    cudaGetSymbolAddress((void**)&als, g_als);
    cudaGetSymbolAddress((void**)&ald, g_ald);
    cudaGetSymbolAddress((void**)&ev, g_ev);
    cudaGetSymbolAddress((void**)&gatout, g_gatout);
    cudaGetSymbolAddress((void**)&agg, g_agg);
    cudaGetSymbolAddress((void**)&s1, g_s1);
    cudaGetSymbolAddress((void**)&agg2, g_agg2);
    cudaGetSymbolAddress((void**)&s2, g_s2);
    cudaGetSymbolAddress((void**)&pooled, g_pooled);
    cudaGetSymbolAddress((void**)&cnt, g_cnt);

    static cudaStream_t sideq = nullptr;
    static cudaEvent_t evA = nullptr, evB = nullptr, evC = nullptr, evD = nullptr;
    if (!sideq) {
        cudaStreamCreateWithFlags(&sideq, cudaStreamNonBlocking);
        cudaEventCreateWithFlags(&evA, cudaEventDisableTiming);
        cudaEventCreateWithFlags(&evB, cudaEventDisableTiming);
        cudaEventCreateWithFlags(&evC, cudaEventDisableTiming);
        cudaEventCreateWithFlags(&evD, cudaEventDisableTiming);
    }

    const int T = 256;
    int nodeWarpBlocks = (N * 32 + T - 1) / T;
    int gRows = (N + 127) / 128;

    // ---- fork: CSR build on side stream; weights cvt + GCN0 GEMM on main ----
    cudaEventRecord(evA, 0);
    cudaStreamWaitEvent(sideq, evA, 0);
    cudaMemsetAsync(deg, 0, N * sizeof(int), sideq);
    deg_kernel<<<(E + T - 1) / T, T, 0, sideq>>>(ei, deg, E);
    scan_kernel<<<1, 1024, 0, sideq>>>(deg, rowstart, cursor, dinv, sinv, N);
    csr_fill<<<(E + T - 1) / T, T, 0, sideq>>>(ei, cursor, csr, E);
    cudaEventRecord(evB, sideq);

    cvt_weights<<<(W_TOTAL + T - 1) / T, T>>>(gcn_w0, gcn_w1, gat_w, s1wl, s1wr, s2wl, s2wr, wh);

    gemm_f16<128, 128, false, false, false, true, false><<<dim3(gRows, 2), 256>>>(
        x, wh + WO_GCN0, nullptr, nullptr, nullptr, tmp, N, nullptr, nullptr, nullptr, nullptr);

    cudaStreamWaitEvent(0, evB, 0);
    gcn_gather<<<nodeWarpBlocks, T>>>(tmp, csr, rowstart, dinv, gcn_b0, h0, N);

    gemm_f16<128, 128, false, false, false, true, true><<<dim3(gRows, 2), 256>>>(
        h0, wh + WO_GCN1, nullptr, nullptr, nullptr, tmp, N, nullptr, nullptr, nullptr, nullptr);
    gcn_gather<<<nodeWarpBlocks, T>>>(tmp, csr, rowstart, dinv, gcn_b1, h1, N);

    // ---- fork: SAGE chain on side stream, GAT on main ----
    cudaEventRecord(evC, 0);
    cudaStreamWaitEvent(sideq, evC, 0);
    sage_gather128<<<nodeWarpBlocks, T, 0, sideq>>>(h1, csr, rowstart, sinv, agg, N);
    gemm_f16<128, 64, true, true, false, true, true><<<dim3(gRows, 1), 256, 0, sideq>>>(
        agg, wh + WO_S1WL, h1, wh + WO_S1WR, s1b, s1, N, nullptr, nullptr, nullptr, nullptr);
    sage_gather64<<<nodeWarpBlocks, T, 0, sideq>>>(s1, csr, rowstart, sinv, agg2, N);
    gemm_f16<64, 64, true, false, false, false, true><<<dim3(gRows, 1), 256, 0, sideq>>>(
        agg2, wh + WO_S2WL, s1, wh + WO_S2WR, s2b, s2, N, nullptr, nullptr, nullptr, nullptr);
    cudaEventRecord(evD, sideq);

    gemm_f16<128, 512, false, false, true, true, true><<<dim3(gRows, 8), 256>>>(
        h1, wh + WO_GATW, nullptr, nullptr, nullptr, gath, N, att_src, att_dst, als, ald);
    gat_fused<<<nodeWarpBlocks, T>>>(csr, rowstart, als, ald, gath, gat_b, ev, gatout, N);

    // ---- join, pool, project ----
    cudaMemsetAsync(pooled, 0, GG * 128 * sizeof(float));
    cudaMemsetAsync(cnt, 0, GG * sizeof(float));
    cudaStreamWaitEvent(0, evD, 0);
    pool_kernel<<<(N + 31) / 32, 128>>>(gatout, s2, batch, pooled, cnt, N);
    final_kernel<<<GG, 64>>>(pooled, cnt, projw, projb, out);
}